// round 8
// baseline (speedup 1.0000x reference)
#include <cuda_runtime.h>
#include <math.h>

#define BB 32
#define CC 64
#define HH 128
#define WW 128
#define QD 8
#define NEGV (-1e4f)

// scratch
__device__ float g_Qt[BB*HH*WW*QD];   // [b,h,w,q] 16.8 MB
__device__ float g_Kt[BB*HH*WW*QD];   // [b,h,w,q] 16.8 MB
__device__ float g_GW[BB*HH*CC*QD];   // [b,h,e,q] 8.4 MB
__device__ float g_sW[BB*HH*QD];
__device__ float g_GH[BB*WW*CC*QD];   // [b,w,e,q] 8.4 MB
__device__ float g_sH[BB*WW*QD];

__device__ __forceinline__ float softplus_f(float v) {
    return fmaxf(v, 0.f) + log1pf(expf(-fabsf(v)));
}
__device__ __forceinline__ unsigned long long pk2(float lo, float hi) {
    unsigned long long r;
    asm("mov.b64 %0, {%1, %2};" : "=l"(r) : "f"(lo), "f"(hi));
    return r;
}
__device__ __forceinline__ float2 upk2(unsigned long long v) {
    float2 r;
    asm("mov.b64 {%0, %1}, %2;" : "=f"(r.x), "=f"(r.y) : "l"(v));
    return r;
}
#define FMA2(d, a, b, c) \
    asm("fma.rn.f32x2 %0, %1, %2, %3;" : "=l"(d) : "l"(a), "l"(b), "l"(c))

// ---------------------------------------------------------------------------
// P1: per (b,h). Q,K projections (softplus) + GW[e,q] = sum_w x[e,w]K[q,w],
// sW[q] = sum_w K[q,w]. Writes Qt/Kt channels-last.
// smem: XS@0:64*132=8448  WQT@8448:512  WKT@8960:512  BQS@9472:8  BKS@9480:8
//       KS@9488:8*132=1056   -> 10544 floats = 42176 B
// ---------------------------------------------------------------------------
#define S1_FLOATS 10544

__global__ __launch_bounds__(256) void cc_p1_kernel(
    const float* __restrict__ x,
    const float* __restrict__ wq, const float* __restrict__ bq,
    const float* __restrict__ wk, const float* __restrict__ bk)
{
    extern __shared__ float sm[];
    float* XS  = sm;
    float* WQT = sm + 8448;   // [c*8+o]
    float* WKT = sm + 8960;
    float* BQS = sm + 9472;
    float* BKS = sm + 9480;
    float* KS  = sm + 9488;   // [q*132+w]

    const int b = blockIdx.y, h = blockIdx.x, tid = threadIdx.x;

    const float* xrow = x + ((size_t)(b*CC)*HH + h)*WW;
    for (int i = tid; i < CC*WW; i += 256) {
        int c = i >> 7, w = i & 127;
        XS[c*132 + w] = xrow[(size_t)c*HH*WW + w];
    }
    for (int i = tid; i < 512; i += 256) {
        int c = i >> 3, o = i & 7;
        WQT[i] = wq[o*CC + c];
        WKT[i] = wk[o*CC + c];
    }
    if (tid < 8) { BQS[tid] = bq[tid]; BKS[tid] = bk[tid]; }
    __syncthreads();

    // projections: thread = (w, half); half 0 -> Q, half 1 -> K
    {
        const int w = tid & 127, half = tid >> 7;
        const float* WT = half ? WKT : WQT;
        const float* BT = half ? BKS : BQS;
        float acc[8];
        #pragma unroll
        for (int o = 0; o < 8; o++) acc[o] = BT[o];
        #pragma unroll 4
        for (int c = 0; c < CC; c++) {
            float xv  = XS[c*132 + w];
            float4 wa = *(const float4*)&WT[c*8];
            float4 wb = *(const float4*)&WT[c*8 + 4];
            acc[0] = fmaf(wa.x, xv, acc[0]); acc[1] = fmaf(wa.y, xv, acc[1]);
            acc[2] = fmaf(wa.z, xv, acc[2]); acc[3] = fmaf(wa.w, xv, acc[3]);
            acc[4] = fmaf(wb.x, xv, acc[4]); acc[5] = fmaf(wb.y, xv, acc[5]);
            acc[6] = fmaf(wb.z, xv, acc[6]); acc[7] = fmaf(wb.w, xv, acc[7]);
        }
        #pragma unroll
        for (int o = 0; o < 8; o++) acc[o] = softplus_f(acc[o]);
        float* dst = (half ? g_Kt : g_Qt) + ((size_t)(b*HH + h)*WW + w)*QD;
        *(float4*)dst       = make_float4(acc[0], acc[1], acc[2], acc[3]);
        *(float4*)(dst + 4) = make_float4(acc[4], acc[5], acc[6], acc[7]);
        if (half) {
            #pragma unroll
            for (int o = 0; o < 8; o++) KS[o*132 + w] = acc[o];
        }
    }
    __syncthreads();

    // GW
    {
        const int e = tid >> 2, q0 = tid & 3, q1 = q0 + 4;
        float a0 = 0.f, a1 = 0.f;
        #pragma unroll 8
        for (int ww = 0; ww < WW; ww += 4) {
            float4 xv = *(const float4*)&XS[e*132 + ww];
            float4 k0 = *(const float4*)&KS[q0*132 + ww];
            float4 k1 = *(const float4*)&KS[q1*132 + ww];
            a0 = fmaf(xv.x,k0.x, fmaf(xv.y,k0.y, fmaf(xv.z,k0.z, fmaf(xv.w,k0.w, a0))));
            a1 = fmaf(xv.x,k1.x, fmaf(xv.y,k1.y, fmaf(xv.z,k1.z, fmaf(xv.w,k1.w, a1))));
        }
        float* gw = g_GW + ((size_t)(b*HH + h)*CC + e)*QD;
        gw[q0] = a0;
        gw[q1] = a1;
    }
    if (tid < 8) {
        float s = 0.f;
        for (int ww = 0; ww < WW; ww++) s += KS[tid*132 + ww];
        g_sW[(b*HH + h)*QD + tid] = s;
    }
}

// ---------------------------------------------------------------------------
// P2: per (b, 8-wide w tile). GH[e,q;b,w] = sum_k x[e,k,w]K[q,k,w] (k over H),
// sH[q;b,w] = sum_k K[q,k,w].
// smem: XS2@0: 64*16*8 = 8192 ([e*128+kk*8+w]), KS2@8192: 16*8*8 = 1024
//       ([kk*64+q*8+w])  -> 9216 floats = 36864 B
// ---------------------------------------------------------------------------
#define S2_FLOATS 9216

__global__ __launch_bounds__(256) void cc_p2_kernel(const float* __restrict__ x)
{
    extern __shared__ float sm[];
    float* XS2 = sm;
    float* KS2 = sm + 8192;

    const int b = blockIdx.y, wt0 = blockIdx.x * 8, tid = threadIdx.x;
    const int eg = tid >> 5, wl = (tid >> 2) & 7, qp = tid & 3;

    float acc0[8], acc1[8];
    #pragma unroll
    for (int i = 0; i < 8; i++) { acc0[i] = 0.f; acc1[i] = 0.f; }
    float sa0 = 0.f, sa1 = 0.f;

    for (int k0 = 0; k0 < HH; k0 += 16) {
        for (int i = tid; i < 2048; i += 256) {     // XS2 fill (float4 units)
            int e = i >> 5, kk = (i >> 1) & 15, j = i & 1;
            const float4* src = (const float4*)(x + ((size_t)(b*CC + e)*HH + k0 + kk)*WW + wt0 + j*4);
            *(float4*)&XS2[e*128 + kk*8 + j*4] = *src;
        }
        for (int i = tid; i < 1024; i += 256) {     // KS2 fill
            int kk = i >> 6, ww = (i >> 3) & 7, q = i & 7;
            KS2[kk*64 + q*8 + ww] =
                g_Kt[((size_t)(b*HH + k0 + kk)*WW + wt0 + ww)*QD + q];
        }
        __syncthreads();
        #pragma unroll
        for (int kk = 0; kk < 16; kk++) {
            float kv0 = KS2[kk*64 + qp*8 + wl];
            float kv1 = KS2[kk*64 + (qp+4)*8 + wl];
            sa0 += kv0; sa1 += kv1;
            #pragma unroll
            for (int e2 = 0; e2 < 8; e2++) {
                float xv = XS2[(eg*8 + e2)*128 + kk*8 + wl];
                acc0[e2] = fmaf(xv, kv0, acc0[e2]);
                acc1[e2] = fmaf(xv, kv1, acc1[e2]);
            }
        }
        __syncthreads();
    }
    #pragma unroll
    for (int e2 = 0; e2 < 8; e2++) {
        float* gh = g_GH + ((size_t)(b*WW + wt0 + wl)*CC + eg*8 + e2)*QD;
        gh[qp]     = acc0[e2];
        gh[qp + 4] = acc1[e2];
    }
    if (eg == 0) {
        g_sH[(b*WW + wt0 + wl)*QD + qp]     = sa0;
        g_sH[(b*WW + wt0 + wl)*QD + qp + 4] = sa1;
    }
}

// ---------------------------------------------------------------------------
// P3: per (b,h).
//  Phase A: T[e,w] = sum_q Q[q,w](GH[e,q;b,w]+GW[e,q;b,h]) + NEG*x[e,w]
//           S[w]   = sum_q Q[q,w](sH+sW)[q] + NEG
//  Phase B: out[c,w] = gamma*( sum_e wvT[e][c]*T[e,w] + bv[c]*S[w] ) + x[c,w]
//           (packed fma.rn.f32x2, acc pairs over adjacent c)
// smem: XS@0:8448  TS@8448:8448  WVS@16896:4096 ([e*64+o])  BVS@20992:64
//       QS2@21056:1024 ([w*8+q])  SS@22080:128  GHb@22208:4160 ([q*516+wp*64+e])
//   -> 26368 floats = 105472 B
// ---------------------------------------------------------------------------
#define S3_FLOATS 26368

__global__ __launch_bounds__(256, 2) void cc_p3_kernel(
    const float* __restrict__ x,
    const float* __restrict__ wv, const float* __restrict__ bv,
    const float* __restrict__ gamma, float* __restrict__ out)
{
    extern __shared__ float sm[];
    float* XS  = sm;            // [e*132+w]
    float* TS  = sm + 8448;     // [e*132+w]
    float* WVS = sm + 16896;    // wv transposed: [e*64+o]
    float* BVS = sm + 20992;
    float* QS2 = sm + 21056;    // [w*8+q]
    float* SS  = sm + 22080;
    float* GHb = sm + 22208;    // [q*516 + wp*64 + e]

    const int b = blockIdx.y, h = blockIdx.x, tid = threadIdx.x;

    const float* xrow = x + ((size_t)(b*CC)*HH + h)*WW;
    for (int i = tid; i < CC*WW; i += 256) {
        int c = i >> 7, w = i & 127;
        XS[c*132 + w] = xrow[(size_t)c*HH*WW + w];
    }
    for (int i = tid; i < 4096; i += 256) {     // transpose read (L2-hot)
        int e = i >> 6, o = i & 63;
        WVS[i] = wv[o*CC + e];
    }
    if (tid < 64) BVS[tid] = bv[tid];
    {
        const float* qt = g_Qt + (size_t)(b*HH + h)*WW*QD;
        for (int i = tid; i < 1024; i += 256) QS2[i] = qt[i];
    }
    // per-thread GW row (Phase A thread: e = tid & 63)
    float gwr[8];
    {
        const float* gw = g_GW + ((size_t)(b*HH + h)*CC + (tid & 63))*QD;
        float4 a = *(const float4*)gw;
        float4 bq4 = *(const float4*)(gw + 4);
        gwr[0]=a.x; gwr[1]=a.y; gwr[2]=a.z; gwr[3]=a.w;
        gwr[4]=bq4.x; gwr[5]=bq4.y; gwr[6]=bq4.z; gwr[7]=bq4.w;
    }
    float swr[8];
    {
        const float* swp = g_sW + (b*HH + h)*QD;
        float4 a = *(const float4*)swp;
        float4 c4 = *(const float4*)(swp + 4);
        swr[0]=a.x; swr[1]=a.y; swr[2]=a.z; swr[3]=a.w;
        swr[4]=c4.x; swr[5]=c4.y; swr[6]=c4.z; swr[7]=c4.w;
    }
    __syncthreads();

    // S[w]
    if (tid < 128) {
        const int w = tid;
        const float* sh = g_sH + ((size_t)b*WW + w)*QD;
        float s = NEGV;
        #pragma unroll
        for (int q = 0; q < 8; q++) s = fmaf(QS2[w*8 + q], sh[q] + swr[q], s);
        SS[w] = s;
    }

    // Phase A
    const int e = tid & 63, wi = tid >> 6;
    for (int wc = 0; wc < WW; wc += 8) {
        __syncthreads();
        {
            const float* src = g_GH + ((size_t)b*WW + wc)*CC*QD;
            for (int i = tid; i < 4096; i += 256) {
                int wp = i >> 9, ee = (i >> 3) & 63, q = i & 7;
                GHb[q*516 + wp*64 + ee] = src[i];
            }
        }
        __syncthreads();
        #pragma unroll
        for (int t2 = 0; t2 < 2; t2++) {
            int wp = wi*2 + t2, w = wc + wp;
            const float* qv = &QS2[w*8];
            float tacc = NEGV * XS[e*132 + w];
            #pragma unroll
            for (int q = 0; q < 8; q++)
                tacc = fmaf(qv[q], GHb[q*516 + wp*64 + e] + gwr[q], tacc);
            TS[e*132 + w] = tacc;
        }
    }
    __syncthreads();

    // Phase B: 64x64x128 GEMM with packed f32x2
    typedef unsigned long long u64;
    const int og = tid >> 5, lane = tid & 31, w0 = lane * 4;
    u64 acc2[4][4];
    {
        float4 b0 = *(const float4*)&BVS[og*8];
        float4 b1 = *(const float4*)&BVS[og*8 + 4];
        float bo[8] = {b0.x,b0.y,b0.z,b0.w,b1.x,b1.y,b1.z,b1.w};
        float4 s4 = *(const float4*)&SS[w0];
        float sj[4] = {s4.x,s4.y,s4.z,s4.w};
        #pragma unroll
        for (int p = 0; p < 4; p++)
            #pragma unroll
            for (int j = 0; j < 4; j++)
                acc2[p][j] = pk2(bo[2*p]*sj[j], bo[2*p+1]*sj[j]);
    }
    {
        const float4* wrow = (const float4*)&WVS[og*8];   // +16 float4 per e
        const float4* trow = (const float4*)&TS[w0];      // +33 float4 per e
        #pragma unroll 4
        for (int c = 0; c < CC; c++) {
            union { float4 f4; u64 u2[2]; } wa, wb, tv;
            wa.f4 = wrow[c*16];
            wb.f4 = wrow[c*16 + 1];
            tv.f4 = trow[c*33];
            u64 t0 = pk2(tv.f4.x, tv.f4.x);
            u64 t1 = pk2(tv.f4.y, tv.f4.y);
            u64 t2 = pk2(tv.f4.z, tv.f4.z);
            u64 t3 = pk2(tv.f4.w, tv.f4.w);
            FMA2(acc2[0][0], wa.u2[0], t0, acc2[0][0]);
            FMA2(acc2[0][1], wa.u2[0], t1, acc2[0][1]);
            FMA2(acc2[0][2], wa.u2[0], t2, acc2[0][2]);
            FMA2(acc2[0][3], wa.u2[0], t3, acc2[0][3]);
            FMA2(acc2[1][0], wa.u2[1], t0, acc2[1][0]);
            FMA2(acc2[1][1], wa.u2[1], t1, acc2[1][1]);
            FMA2(acc2[1][2], wa.u2[1], t2, acc2[1][2]);
            FMA2(acc2[1][3], wa.u2[1], t3, acc2[1][3]);
            FMA2(acc2[2][0], wb.u2[0], t0, acc2[2][0]);
            FMA2(acc2[2][1], wb.u2[0], t1, acc2[2][1]);
            FMA2(acc2[2][2], wb.u2[0], t2, acc2[2][2]);
            FMA2(acc2[2][3], wb.u2[0], t3, acc2[2][3]);
            FMA2(acc2[3][0], wb.u2[1], t0, acc2[3][0]);
            FMA2(acc2[3][1], wb.u2[1], t1, acc2[3][1]);
            FMA2(acc2[3][2], wb.u2[1], t2, acc2[3][2]);
            FMA2(acc2[3][3], wb.u2[1], t3, acc2[3][3]);
        }
    }
    // epilogue: out = gamma*acc + x
    {
        const float g = gamma[0];
        #pragma unroll
        for (int p = 0; p < 4; p++) {
            float2 r0 = upk2(acc2[p][0]);
            float2 r1 = upk2(acc2[p][1]);
            float2 r2 = upk2(acc2[p][2]);
            float2 r3 = upk2(acc2[p][3]);
            const int o = og*8 + 2*p;
            float4 xa = *(const float4*)&XS[o*132 + w0];
            float4 ov;
            ov.x = fmaf(g, r0.x, xa.x);
            ov.y = fmaf(g, r1.x, xa.y);
            ov.z = fmaf(g, r2.x, xa.z);
            ov.w = fmaf(g, r3.x, xa.w);
            *(float4*)&out[((size_t)(b*CC + o)*HH + h)*WW + w0] = ov;
            float4 xb = *(const float4*)&XS[(o+1)*132 + w0];
            ov.x = fmaf(g, r0.y, xb.x);
            ov.y = fmaf(g, r1.y, xb.y);
            ov.z = fmaf(g, r2.y, xb.z);
            ov.w = fmaf(g, r3.y, xb.w);
            *(float4*)&out[((size_t)(b*CC + o + 1)*HH + h)*WW + w0] = ov;
        }
    }
}

// ---------------------------------------------------------------------------
extern "C" void kernel_launch(void* const* d_in, const int* in_sizes, int n_in,
                              void* d_out, int out_size)
{
    const float* x     = (const float*)d_in[0];
    const float* wq    = (const float*)d_in[1];
    const float* bq    = (const float*)d_in[2];
    const float* wk    = (const float*)d_in[3];
    const float* bk    = (const float*)d_in[4];
    const float* wv    = (const float*)d_in[5];
    const float* bv    = (const float*)d_in[6];
    const float* gamma = (const float*)d_in[7];
    float* out = (float*)d_out;

    (void)in_sizes; (void)n_in; (void)out_size;

    cudaFuncSetAttribute(cc_p1_kernel, cudaFuncAttributeMaxDynamicSharedMemorySize,
                         S1_FLOATS * (int)sizeof(float));
    cudaFuncSetAttribute(cc_p2_kernel, cudaFuncAttributeMaxDynamicSharedMemorySize,
                         S2_FLOATS * (int)sizeof(float));
    cudaFuncSetAttribute(cc_p3_kernel, cudaFuncAttributeMaxDynamicSharedMemorySize,
                         S3_FLOATS * (int)sizeof(float));

    cc_p1_kernel<<<dim3(HH, BB), 256, S1_FLOATS * sizeof(float)>>>(
        x, wq, bq, wk, bk);
    cc_p2_kernel<<<dim3(WW/8, BB), 256, S2_FLOATS * sizeof(float)>>>(x);
    cc_p3_kernel<<<dim3(HH, BB), 256, S3_FLOATS * sizeof(float)>>>(
        x, wv, bv, gamma, out);
}

// round 11
// speedup vs baseline: 1.4794x; 1.4794x over previous
#include <cuda_runtime.h>
#include <math.h>

#define BB 32
#define CC 64
#define HH 128
#define WW 128
#define QD 8
#define NEGV (-1e4f)

// scratch
__device__ float g_Qt[BB*HH*WW*QD];   // [b,h,w,q] 16.8 MB
__device__ float g_Kt[BB*HH*WW*QD];   // [b,h,w,q] 16.8 MB
__device__ float g_GW[BB*HH*CC*QD];   // [b,h,e,q] 8.4 MB
__device__ float g_sW[BB*HH*QD];
__device__ float g_GH[BB*WW*CC*QD];   // [b,w,e,q] 8.4 MB
__device__ float g_sH[BB*WW*QD];

__device__ __forceinline__ float softplus_f(float v) {
    return fmaxf(v, 0.f) + log1pf(expf(-fabsf(v)));
}
__device__ __forceinline__ unsigned long long pk2(float lo, float hi) {
    unsigned long long r;
    asm("mov.b64 %0, {%1, %2};" : "=l"(r) : "f"(lo), "f"(hi));
    return r;
}
__device__ __forceinline__ float2 upk2(unsigned long long v) {
    float2 r;
    asm("mov.b64 {%0, %1}, %2;" : "=f"(r.x), "=f"(r.y) : "l"(v));
    return r;
}
#define FMA2(d, a, b, c) \
    asm("fma.rn.f32x2 %0, %1, %2, %3;" : "=l"(d) : "l"(a), "l"(b), "l"(c))

// ---------------------------------------------------------------------------
// P1: per (b,h). Q,K projections (softplus) + GW[e,q] = sum_w x[e,w]K[q,w],
// sW[q] = sum_w K[q,w]. Writes Qt/Kt channels-last.  (unchanged from R8)
// ---------------------------------------------------------------------------
#define S1_FLOATS 10544

__global__ __launch_bounds__(256) void cc_p1_kernel(
    const float* __restrict__ x,
    const float* __restrict__ wq, const float* __restrict__ bq,
    const float* __restrict__ wk, const float* __restrict__ bk)
{
    extern __shared__ float sm[];
    float* XS  = sm;
    float* WQT = sm + 8448;   // [c*8+o]
    float* WKT = sm + 8960;
    float* BQS = sm + 9472;
    float* BKS = sm + 9480;
    float* KS  = sm + 9488;   // [q*132+w]

    const int b = blockIdx.y, h = blockIdx.x, tid = threadIdx.x;

    const float* xrow = x + ((size_t)(b*CC)*HH + h)*WW;
    for (int i = tid; i < CC*WW; i += 256) {
        int c = i >> 7, w = i & 127;
        XS[c*132 + w] = xrow[(size_t)c*HH*WW + w];
    }
    for (int i = tid; i < 512; i += 256) {
        int c = i >> 3, o = i & 7;
        WQT[i] = wq[o*CC + c];
        WKT[i] = wk[o*CC + c];
    }
    if (tid < 8) { BQS[tid] = bq[tid]; BKS[tid] = bk[tid]; }
    __syncthreads();

    {
        const int w = tid & 127, half = tid >> 7;
        const float* WT = half ? WKT : WQT;
        const float* BT = half ? BKS : BQS;
        float acc[8];
        #pragma unroll
        for (int o = 0; o < 8; o++) acc[o] = BT[o];
        #pragma unroll 4
        for (int c = 0; c < CC; c++) {
            float xv  = XS[c*132 + w];
            float4 wa = *(const float4*)&WT[c*8];
            float4 wb = *(const float4*)&WT[c*8 + 4];
            acc[0] = fmaf(wa.x, xv, acc[0]); acc[1] = fmaf(wa.y, xv, acc[1]);
            acc[2] = fmaf(wa.z, xv, acc[2]); acc[3] = fmaf(wa.w, xv, acc[3]);
            acc[4] = fmaf(wb.x, xv, acc[4]); acc[5] = fmaf(wb.y, xv, acc[5]);
            acc[6] = fmaf(wb.z, xv, acc[6]); acc[7] = fmaf(wb.w, xv, acc[7]);
        }
        #pragma unroll
        for (int o = 0; o < 8; o++) acc[o] = softplus_f(acc[o]);
        float* dst = (half ? g_Kt : g_Qt) + ((size_t)(b*HH + h)*WW + w)*QD;
        *(float4*)dst       = make_float4(acc[0], acc[1], acc[2], acc[3]);
        *(float4*)(dst + 4) = make_float4(acc[4], acc[5], acc[6], acc[7]);
        if (half) {
            #pragma unroll
            for (int o = 0; o < 8; o++) KS[o*132 + w] = acc[o];
        }
    }
    __syncthreads();

    {
        const int e = tid >> 2, q0 = tid & 3, q1 = q0 + 4;
        float a0 = 0.f, a1 = 0.f;
        #pragma unroll 8
        for (int ww = 0; ww < WW; ww += 4) {
            float4 xv = *(const float4*)&XS[e*132 + ww];
            float4 k0 = *(const float4*)&KS[q0*132 + ww];
            float4 k1 = *(const float4*)&KS[q1*132 + ww];
            a0 = fmaf(xv.x,k0.x, fmaf(xv.y,k0.y, fmaf(xv.z,k0.z, fmaf(xv.w,k0.w, a0))));
            a1 = fmaf(xv.x,k1.x, fmaf(xv.y,k1.y, fmaf(xv.z,k1.z, fmaf(xv.w,k1.w, a1))));
        }
        float* gw = g_GW + ((size_t)(b*HH + h)*CC + e)*QD;
        gw[q0] = a0;
        gw[q1] = a1;
    }
    if (tid < 8) {
        float s = 0.f;
        for (int ww = 0; ww < WW; ww++) s += KS[tid*132 + ww];
        g_sW[(b*HH + h)*QD + tid] = s;
    }
}

// ---------------------------------------------------------------------------
// P2: per (b, 8-wide w tile, 32-wide e half). GH[e,q;b,w] = sum_k x[e,k,w]K[q,k,w].
// grid (32, BB): blockIdx.x = wt(0..15) | ehalf<<4
// smem: XS2@0: 32*16*8 = 4096 ([e*128+kk*8+w]), KS2@4096: 16*8*8 = 1024
// ---------------------------------------------------------------------------
#define S2_FLOATS 5120

__global__ __launch_bounds__(256) void cc_p2_kernel(const float* __restrict__ x)
{
    extern __shared__ float sm[];
    float* XS2 = sm;
    float* KS2 = sm + 4096;

    const int b = blockIdx.y;
    const int wt0 = (blockIdx.x & 15) * 8;
    const int e0  = (blockIdx.x >> 4) * 32;
    const int tid = threadIdx.x;
    const int eg = tid >> 5, wl = (tid >> 2) & 7, qp = tid & 3;

    float acc0[4], acc1[4];
    #pragma unroll
    for (int i = 0; i < 4; i++) { acc0[i] = 0.f; acc1[i] = 0.f; }
    float sa0 = 0.f, sa1 = 0.f;

    for (int k0 = 0; k0 < HH; k0 += 16) {
        for (int i = tid; i < 1024; i += 256) {     // XS2 fill (float4 units)
            int e = i >> 5, kk = (i >> 1) & 15, j = i & 1;
            *(float4*)&XS2[e*128 + kk*8 + j*4] =
                *(const float4*)(x + ((size_t)(b*CC + e0 + e)*HH + k0 + kk)*WW + wt0 + j*4);
        }
        for (int i = tid; i < 1024; i += 256) {     // KS2 fill
            int kk = i >> 6, ww = (i >> 3) & 7, q = i & 7;
            KS2[kk*64 + q*8 + ww] =
                g_Kt[((size_t)(b*HH + k0 + kk)*WW + wt0 + ww)*QD + q];
        }
        __syncthreads();
        #pragma unroll
        for (int kk = 0; kk < 16; kk++) {
            float kv0 = KS2[kk*64 + qp*8 + wl];
            float kv1 = KS2[kk*64 + (qp+4)*8 + wl];
            sa0 += kv0; sa1 += kv1;
            #pragma unroll
            for (int e2 = 0; e2 < 4; e2++) {
                float xv = XS2[(eg*4 + e2)*128 + kk*8 + wl];
                acc0[e2] = fmaf(xv, kv0, acc0[e2]);
                acc1[e2] = fmaf(xv, kv1, acc1[e2]);
            }
        }
        __syncthreads();
    }
    #pragma unroll
    for (int e2 = 0; e2 < 4; e2++) {
        float* gh = g_GH + ((size_t)(b*WW + wt0 + wl)*CC + e0 + eg*4 + e2)*QD;
        gh[qp]     = acc0[e2];
        gh[qp + 4] = acc1[e2];
    }
    if (eg == 0 && e0 == 0) {
        g_sH[(b*WW + wt0 + wl)*QD + qp]     = sa0;
        g_sH[(b*WW + wt0 + wl)*QD + qp + 4] = sa1;
    }
}

// ---------------------------------------------------------------------------
// P3: per (b,h).
//  Phase A: T[e,w] = sum_q Q[q,w](GH[e,q;b,w]+GW[e,q;b,h]) + NEG*x[e,w]
//           via direct coalesced LDG of GH (no smem staging, no inner barriers)
//  Phase B: out[c,w] = gamma*( sum_e wvT[e][c]*T[e,w] + bv[c]*S[w] ) + x[c,w]
// smem: XS@0:8448  TS@8448:8448  WVS@16896:4096  BVS@20992:64
//       QS2@21056:1024  SS@22080:128   -> 22208 floats = 88832 B
// ---------------------------------------------------------------------------
#define S3_FLOATS 22208

__global__ __launch_bounds__(256, 2) void cc_p3_kernel(
    const float* __restrict__ x,
    const float* __restrict__ wv, const float* __restrict__ bv,
    const float* __restrict__ gamma, float* __restrict__ out)
{
    extern __shared__ float sm[];
    float* XS  = sm;            // [e*132+w]
    float* TS  = sm + 8448;     // [e*132+w]
    float* WVS = sm + 16896;    // wv transposed: [e*64+o]
    float* BVS = sm + 20992;
    float* QS2 = sm + 21056;    // [w*8+q]
    float* SS  = sm + 22080;

    const int b = blockIdx.y, h = blockIdx.x, tid = threadIdx.x;

    const float* xrow = x + ((size_t)(b*CC)*HH + h)*WW;
    for (int i = tid; i < CC*WW; i += 256) {
        int c = i >> 7, w = i & 127;
        XS[c*132 + w] = xrow[(size_t)c*HH*WW + w];
    }
    for (int i = tid; i < 4096; i += 256) {
        int e = i >> 6, o = i & 63;
        WVS[i] = wv[o*CC + e];
    }
    if (tid < 64) BVS[tid] = bv[tid];
    {
        const float* qt = g_Qt + (size_t)(b*HH + h)*WW*QD;
        for (int i = tid; i < 1024; i += 256) QS2[i] = qt[i];
    }

    // Phase A thread map: lane-consecutive e for coalesced GH loads
    const int lane = tid & 31;
    const int e    = ((tid >> 5) & 1) * 32 + lane;   // 0..63, contiguous per warp
    const int wp   = tid >> 6;                       // 0..3

    float gwr[8], swr[8];
    {
        const float* gw = g_GW + ((size_t)(b*HH + h)*CC + e)*QD;
        float4 a = *(const float4*)gw;
        float4 c4 = *(const float4*)(gw + 4);
        gwr[0]=a.x; gwr[1]=a.y; gwr[2]=a.z; gwr[3]=a.w;
        gwr[4]=c4.x; gwr[5]=c4.y; gwr[6]=c4.z; gwr[7]=c4.w;
        const float* swp = g_sW + (b*HH + h)*QD;
        float4 s0 = *(const float4*)swp;
        float4 s1 = *(const float4*)(swp + 4);
        swr[0]=s0.x; swr[1]=s0.y; swr[2]=s0.z; swr[3]=s0.w;
        swr[4]=s1.x; swr[5]=s1.y; swr[6]=s1.z; swr[7]=s1.w;
    }
    __syncthreads();

    // S[w]
    if (tid < 128) {
        const int w = tid;
        const float* sh = g_sH + ((size_t)b*WW + w)*QD;
        float s = NEGV;
        #pragma unroll
        for (int q = 0; q < 8; q++) s = fmaf(QS2[w*8 + q], sh[q] + swr[q], s);
        SS[w] = s;
    }

    // Phase A: direct LDG of GH, pipelined, no barriers
    {
        const float* ghB = g_GH + (size_t)b*WW*CC*QD;
        #pragma unroll 4
        for (int it = 0; it < 32; it++) {
            const int w = wp + it*4;
            const float4* gp = (const float4*)(ghB + ((size_t)w*CC + e)*QD);
            float4 g0 = gp[0];
            float4 g1 = gp[1];
            float4 qa = *(const float4*)&QS2[w*8];
            float4 qb = *(const float4*)&QS2[w*8 + 4];
            float t = NEGV * XS[e*132 + w];
            t = fmaf(qa.x, g0.x + gwr[0], t);
            t = fmaf(qa.y, g0.y + gwr[1], t);
            t = fmaf(qa.z, g0.z + gwr[2], t);
            t = fmaf(qa.w, g0.w + gwr[3], t);
            t = fmaf(qb.x, g1.x + gwr[4], t);
            t = fmaf(qb.y, g1.y + gwr[5], t);
            t = fmaf(qb.z, g1.z + gwr[6], t);
            t = fmaf(qb.w, g1.w + gwr[7], t);
            TS[e*132 + w] = t;
        }
    }
    __syncthreads();

    // Phase B: 64x64x128 GEMM with packed f32x2
    typedef unsigned long long u64;
    const int og = tid >> 5, blane = tid & 31, w0 = blane * 4;
    u64 acc2[4][4];
    {
        float4 b0 = *(const float4*)&BVS[og*8];
        float4 b1 = *(const float4*)&BVS[og*8 + 4];
        float bo[8] = {b0.x,b0.y,b0.z,b0.w,b1.x,b1.y,b1.z,b1.w};
        float4 s4 = *(const float4*)&SS[w0];
        float sj[4] = {s4.x,s4.y,s4.z,s4.w};
        #pragma unroll
        for (int p = 0; p < 4; p++)
            #pragma unroll
            for (int j = 0; j < 4; j++)
                acc2[p][j] = pk2(bo[2*p]*sj[j], bo[2*p+1]*sj[j]);
    }
    {
        const float4* wrow = (const float4*)&WVS[og*8];   // +16 float4 per e
        const float4* trow = (const float4*)&TS[w0];      // +33 float4 per e
        #pragma unroll 4
        for (int c = 0; c < CC; c++) {
            union { float4 f4; u64 u2[2]; } wa, wb, tv;
            wa.f4 = wrow[c*16];
            wb.f4 = wrow[c*16 + 1];
            tv.f4 = trow[c*33];
            u64 t0 = pk2(tv.f4.x, tv.f4.x);
            u64 t1 = pk2(tv.f4.y, tv.f4.y);
            u64 t2 = pk2(tv.f4.z, tv.f4.z);
            u64 t3 = pk2(tv.f4.w, tv.f4.w);
            FMA2(acc2[0][0], wa.u2[0], t0, acc2[0][0]);
            FMA2(acc2[0][1], wa.u2[0], t1, acc2[0][1]);
            FMA2(acc2[0][2], wa.u2[0], t2, acc2[0][2]);
            FMA2(acc2[0][3], wa.u2[0], t3, acc2[0][3]);
            FMA2(acc2[1][0], wa.u2[1], t0, acc2[1][0]);
            FMA2(acc2[1][1], wa.u2[1], t1, acc2[1][1]);
            FMA2(acc2[1][2], wa.u2[1], t2, acc2[1][2]);
            FMA2(acc2[1][3], wa.u2[1], t3, acc2[1][3]);
            FMA2(acc2[2][0], wb.u2[0], t0, acc2[2][0]);
            FMA2(acc2[2][1], wb.u2[0], t1, acc2[2][1]);
            FMA2(acc2[2][2], wb.u2[0], t2, acc2[2][2]);
            FMA2(acc2[2][3], wb.u2[0], t3, acc2[2][3]);
            FMA2(acc2[3][0], wb.u2[1], t0, acc2[3][0]);
            FMA2(acc2[3][1], wb.u2[1], t1, acc2[3][1]);
            FMA2(acc2[3][2], wb.u2[1], t2, acc2[3][2]);
            FMA2(acc2[3][3], wb.u2[1], t3, acc2[3][3]);
        }
    }
    {
        const float g = gamma[0];
        #pragma unroll
        for (int p = 0; p < 4; p++) {
            float2 r0 = upk2(acc2[p][0]);
            float2 r1 = upk2(acc2[p][1]);
            float2 r2 = upk2(acc2[p][2]);
            float2 r3 = upk2(acc2[p][3]);
            const int o = og*8 + 2*p;
            float4 xa = *(const float4*)&XS[o*132 + w0];
            float4 ov;
            ov.x = fmaf(g, r0.x, xa.x);
            ov.y = fmaf(g, r1.x, xa.y);
            ov.z = fmaf(g, r2.x, xa.z);
            ov.w = fmaf(g, r3.x, xa.w);
            *(float4*)&out[((size_t)(b*CC + o)*HH + h)*WW + w0] = ov;
            float4 xb = *(const float4*)&XS[(o+1)*132 + w0];
            ov.x = fmaf(g, r0.y, xb.x);
            ov.y = fmaf(g, r1.y, xb.y);
            ov.z = fmaf(g, r2.y, xb.z);
            ov.w = fmaf(g, r3.y, xb.w);
            *(float4*)&out[((size_t)(b*CC + o + 1)*HH + h)*WW + w0] = ov;
        }
    }
}

// ---------------------------------------------------------------------------
extern "C" void kernel_launch(void* const* d_in, const int* in_sizes, int n_in,
                              void* d_out, int out_size)
{
    const float* x     = (const float*)d_in[0];
    const float* wq    = (const float*)d_in[1];
    const float* bq    = (const float*)d_in[2];
    const float* wk    = (const float*)d_in[3];
    const float* bk    = (const float*)d_in[4];
    const float* wv    = (const float*)d_in[5];
    const float* bv    = (const float*)d_in[6];
    const float* gamma = (const float*)d_in[7];
    float* out = (float*)d_out;

    (void)in_sizes; (void)n_in; (void)out_size;

    cudaFuncSetAttribute(cc_p1_kernel, cudaFuncAttributeMaxDynamicSharedMemorySize,
                         S1_FLOATS * (int)sizeof(float));
    cudaFuncSetAttribute(cc_p2_kernel, cudaFuncAttributeMaxDynamicSharedMemorySize,
                         S2_FLOATS * (int)sizeof(float));
    cudaFuncSetAttribute(cc_p3_kernel, cudaFuncAttributeMaxDynamicSharedMemorySize,
                         S3_FLOATS * (int)sizeof(float));

    cc_p1_kernel<<<dim3(HH, BB), 256, S1_FLOATS * sizeof(float)>>>(
        x, wq, bq, wk, bk);
    cc_p2_kernel<<<dim3(32, BB), 256, S2_FLOATS * sizeof(float)>>>(x);
    cc_p3_kernel<<<dim3(HH, BB), 256, S3_FLOATS * sizeof(float)>>>(
        x, wv, bv, gamma, out);
}